// round 1
// baseline (speedup 1.0000x reference)
#include <cuda_runtime.h>
#include <math.h>

#define Bdim 16
#define Ndim 128
#define Cdim 256
#define BN   (Bdim*Ndim)            // 2048
#define MROWS (Bdim*Ndim*Ndim)      // 262144

#define SASTR 36     // A tile row stride (64 x 32 chunk, padded)
#define SBSTR 260    // B tile / attn tile row stride (padded, float4-aligned)

#define EDGE_SMEM ((64*SASTR + 32*SBSTR + 64*SBSTR)*4)   // 109056 B
#define SM_SMEM   ((128*Cdim + Cdim)*4)                  // 132096 B

// Scratch (allocation-free rule: __device__ globals)
__device__ float g_q[BN*Cdim];
__device__ float g_k[BN*Cdim];
__device__ float g_v[BN*Cdim];
__device__ float g_WonT[Cdim*Cdim];
__device__ float g_attn[MROWS*Cdim];   // 268 MB scratch for softmax pass

// ---------------- Won transpose (tiny) ----------------
__global__ void wont_kernel(const float* __restrict__ W) {
    int c = blockIdx.x, k = threadIdx.x;
    g_WonT[k*Cdim + c] = W[c*Cdim + k];
}

// ---------------- tile helpers ----------------
__device__ __forceinline__ void load_tileA(float* sA, const float* __restrict__ X,
                                           int row0, int kc, int tid) {
    #pragma unroll
    for (int it = 0; it < 2; it++) {
        int idx = tid + it*256;
        int r = idx >> 3, k4 = idx & 7;
        float4 t = *(const float4*)(X + (size_t)(row0 + r)*Cdim + kc*32 + k4*4);
        *(float4*)(sA + r*SASTR + k4*4) = t;
    }
}

__device__ __forceinline__ void load_tileB(float* sB, const float* __restrict__ W,
                                           int kc, int tid) {
    #pragma unroll
    for (int it = 0; it < 8; it++) {
        int idx = tid + it*256;
        int c = idx >> 3, k4 = idx & 7;
        float4 t = *(const float4*)(W + c*Cdim + kc*32 + k4*4);
        sB[(k4*4+0)*SBSTR + c] = t.x;
        sB[(k4*4+1)*SBSTR + c] = t.y;
        sB[(k4*4+2)*SBSTR + c] = t.z;
        sB[(k4*4+3)*SBSTR + c] = t.w;
    }
}

__device__ __forceinline__ void mma_chunk_sA(const float* sA, const float* sB,
                                             float acc[8][8], int tx, int ty) {
    #pragma unroll
    for (int k = 0; k < 32; k++) {
        float a[8];
        #pragma unroll
        for (int mm = 0; mm < 4; mm++) {
            a[mm]   = sA[(ty*4+mm)*SASTR + k];
            a[4+mm] = sA[(32+ty*4+mm)*SASTR + k];
        }
        float4 p0 = *(const float4*)(sB + k*SBSTR + tx*4);
        float4 p1 = *(const float4*)(sB + k*SBSTR + 128 + tx*4);
        float bb[8] = {p0.x,p0.y,p0.z,p0.w,p1.x,p1.y,p1.z,p1.w};
        #pragma unroll
        for (int m = 0; m < 8; m++)
            #pragma unroll
            for (int n = 0; n < 8; n++)
                acc[m][n] = fmaf(a[m], bb[n], acc[m][n]);
    }
}

__device__ __forceinline__ void mma_chunk_attn(const float* sAttn, const float* sB,
                                               float acc[8][8], int tx, int ty, int kc) {
    #pragma unroll
    for (int kk = 0; kk < 32; kk++) {
        int k = kc*32 + kk;
        float a[8];
        #pragma unroll
        for (int mm = 0; mm < 4; mm++) {
            a[mm]   = sAttn[(ty*4+mm)*SBSTR + k];
            a[4+mm] = sAttn[(32+ty*4+mm)*SBSTR + k];
        }
        float4 p0 = *(const float4*)(sB + kk*SBSTR + tx*4);
        float4 p1 = *(const float4*)(sB + kk*SBSTR + 128 + tx*4);
        float bb[8] = {p0.x,p0.y,p0.z,p0.w,p1.x,p1.y,p1.z,p1.w};
        #pragma unroll
        for (int m = 0; m < 8; m++)
            #pragma unroll
            for (int n = 0; n < 8; n++)
                acc[m][n] = fmaf(a[m], bb[n], acc[m][n]);
    }
}

// ---------------- q/k/v projection ----------------
__global__ __launch_bounds__(256) void proj_kernel(
    const float* __restrict__ X,
    const float* __restrict__ W0, const float* __restrict__ b0,
    const float* __restrict__ W1, const float* __restrict__ b1,
    const float* __restrict__ W2, const float* __restrict__ b2)
{
    __shared__ float sA[64*SASTR];
    __shared__ float sB[32*SBSTR];
    int which = blockIdx.y;
    const float* W    = (which==0) ? W0 : (which==1 ? W1 : W2);
    const float* bias = (which==0) ? b0 : (which==1 ? b1 : b2);
    float* Y          = (which==0) ? g_q : (which==1 ? g_k : g_v);

    int tid = threadIdx.x;
    int tx = tid & 31, ty = tid >> 5;
    int row0 = blockIdx.x * 64;

    float acc[8][8];
    #pragma unroll
    for (int m = 0; m < 8; m++)
        #pragma unroll
        for (int n = 0; n < 8; n++) acc[m][n] = 0.f;

    for (int kc = 0; kc < 8; kc++) {
        __syncthreads();
        load_tileA(sA, X, row0, kc, tid);
        load_tileB(sB, W, kc, tid);
        __syncthreads();
        mma_chunk_sA(sA, sB, acc, tx, ty);
    }

    #pragma unroll
    for (int mh = 0; mh < 2; mh++)
    #pragma unroll
    for (int mm = 0; mm < 4; mm++) {
        int m = mh*4 + mm;
        int rloc = mh*32 + ty*4 + mm;
        size_t grow = (size_t)(row0 + rloc) * Cdim;
        #pragma unroll
        for (int nh = 0; nh < 2; nh++) {
            int col0 = nh*128 + tx*4;
            float4 o;
            o.x = acc[m][nh*4+0] + bias[col0+0];
            o.y = acc[m][nh*4+1] + bias[col0+1];
            o.z = acc[m][nh*4+2] + bias[col0+2];
            o.w = acc[m][nh*4+3] + bias[col0+3];
            *(float4*)(Y + grow + col0) = o;
        }
    }
}

// ---------------- fused edge pipeline ----------------
// GEMM1: e = edge @ We^T + be    (per 64-row tile)
// gate:  attn = q*k*inv_sqrt_dk*(e^2+e)   -> g_attn + smem
// GEMM2: edge_out = attn @ Woe^T + boe
__global__ __launch_bounds__(256, 2) void edge_kernel(
    const float* __restrict__ edge,
    const float* __restrict__ We, const float* __restrict__ be,
    const float* __restrict__ Woe, const float* __restrict__ boe,
    float* __restrict__ edge_out)
{
    extern __shared__ float sm[];
    float* sA    = sm;
    float* sB    = sm + 64*SASTR;
    float* sAttn = sB + 32*SBSTR;

    int tid = threadIdx.x;
    int tx = tid & 31, ty = tid >> 5;
    int row0 = blockIdx.x * 64;
    int bi = row0 / Ndim;            // b*N + i  (64 | 128 -> constant per CTA)
    int b  = bi >> 7;
    int j0 = row0 & (Ndim - 1);

    float acc[8][8];
    #pragma unroll
    for (int m = 0; m < 8; m++)
        #pragma unroll
        for (int n = 0; n < 8; n++) acc[m][n] = 0.f;

    for (int kc = 0; kc < 8; kc++) {
        __syncthreads();
        load_tileA(sA, edge, row0, kc, tid);
        load_tileB(sB, We, kc, tid);
        __syncthreads();
        mma_chunk_sA(sA, sB, acc, tx, ty);
    }

    // ---- gating epilogue ----
    const float inv = 0.1767766952966369f;   // 1/sqrt(32)
    const float* qrow = g_q + (size_t)bi * Cdim;
    const float* kb   = g_k + (size_t)(b*Ndim + j0) * Cdim;

    #pragma unroll
    for (int mh = 0; mh < 2; mh++)
    #pragma unroll
    for (int mm = 0; mm < 4; mm++) {
        int m = mh*4 + mm;
        int rloc = mh*32 + ty*4 + mm;
        const float* krow = kb + (size_t)rloc * Cdim;
        size_t grow = (size_t)(row0 + rloc) * Cdim;
        #pragma unroll
        for (int nh = 0; nh < 2; nh++) {
            int col0 = nh*128 + tx*4;
            float avv[4];
            #pragma unroll
            for (int nn = 0; nn < 4; nn++) {
                int n = nh*4 + nn;
                int col = col0 + nn;
                float e = acc[m][n] + be[col];
                avv[nn] = qrow[col]*krow[col]*inv*(e*e + e);
                acc[m][n] = 0.f;   // reset for GEMM2
            }
            float4 av = make_float4(avv[0], avv[1], avv[2], avv[3]);
            *(float4*)(g_attn + grow + col0) = av;
            *(float4*)(sAttn + rloc*SBSTR + col0) = av;
        }
    }

    // ---- GEMM2 ----
    for (int kc = 0; kc < 8; kc++) {
        __syncthreads();              // sAttn writes done / sB reads done
        load_tileB(sB, Woe, kc, tid);
        __syncthreads();
        mma_chunk_attn(sAttn, sB, acc, tx, ty, kc);
    }

    #pragma unroll
    for (int mh = 0; mh < 2; mh++)
    #pragma unroll
    for (int mm = 0; mm < 4; mm++) {
        int m = mh*4 + mm;
        int rloc = mh*32 + ty*4 + mm;
        size_t grow = (size_t)(row0 + rloc) * Cdim;
        #pragma unroll
        for (int nh = 0; nh < 2; nh++) {
            int col0 = nh*128 + tx*4;
            float4 o;
            o.x = acc[m][nh*4+0] + boe[col0+0];
            o.y = acc[m][nh*4+1] + boe[col0+1];
            o.z = acc[m][nh*4+2] + boe[col0+2];
            o.w = acc[m][nh*4+3] + boe[col0+3];
            *(float4*)(edge_out + grow + col0) = o;
        }
    }
}

// ---------------- softmax over j + v-aggregation + node projection ----------------
__global__ __launch_bounds__(256) void softmax_kernel(
    const float* __restrict__ bon, float* __restrict__ node_out)
{
    extern __shared__ float sm[];
    float* sX   = sm;                 // [128][256]
    float* sAgg = sm + 128*Cdim;      // [256]

    int tid = threadIdx.x;
    int bi = blockIdx.x;              // b*N + i
    int b  = bi >> 7;
    size_t base = (size_t)bi * Ndim * Cdim;

    const float4* src = (const float4*)(g_attn + base);
    float4* dst = (float4*)sX;
    #pragma unroll
    for (int it = 0; it < 32; it++) dst[tid + it*256] = src[tid + it*256];
    __syncthreads();

    int c = tid;
    float mx = -INFINITY;
    #pragma unroll 4
    for (int j = 0; j < Ndim; j++) mx = fmaxf(mx, sX[j*Cdim + c]);

    const float* vb = g_v + (size_t)(b*Ndim) * Cdim;
    float s = 0.f, agg = 0.f;
    #pragma unroll 4
    for (int j = 0; j < Ndim; j++) {
        float t = __expf(sX[j*Cdim + c] - mx);
        s += t;
        agg += t * vb[j*Cdim + c];
    }
    agg /= s;
    sAgg[c] = agg;
    __syncthreads();

    float out = bon[c];
    #pragma unroll 8
    for (int k = 0; k < Cdim; k++)
        out = fmaf(sAgg[k], g_WonT[k*Cdim + c], out);
    node_out[(size_t)bi*Cdim + c] = out;
}

// ---------------- launch ----------------
extern "C" void kernel_launch(void* const* d_in, const int* in_sizes, int n_in,
                              void* d_out, int out_size)
{
    const float* node = (const float*)d_in[0];
    const float* edge = (const float*)d_in[1];
    const float* Wq  = (const float*)d_in[2];  const float* bq  = (const float*)d_in[3];
    const float* Wk  = (const float*)d_in[4];  const float* bk  = (const float*)d_in[5];
    const float* Wv  = (const float*)d_in[6];  const float* bv  = (const float*)d_in[7];
    const float* We  = (const float*)d_in[8];  const float* be  = (const float*)d_in[9];
    const float* Woe = (const float*)d_in[10]; const float* boe = (const float*)d_in[11];
    const float* Won = (const float*)d_in[12]; const float* bon = (const float*)d_in[13];

    float* out = (float*)d_out;
    float* node_out = out;                       // [B,N,C]
    float* edge_out = out + (size_t)BN*Cdim;     // [B,N,N,C]

    cudaFuncSetAttribute(edge_kernel,   cudaFuncAttributeMaxDynamicSharedMemorySize, EDGE_SMEM);
    cudaFuncSetAttribute(softmax_kernel, cudaFuncAttributeMaxDynamicSharedMemorySize, SM_SMEM);

    wont_kernel<<<Cdim, Cdim>>>(Won);
    dim3 pg(BN/64, 3);
    proj_kernel<<<pg, 256>>>(node, Wq, bq, Wk, bk, Wv, bv);
    edge_kernel<<<MROWS/64, 256, EDGE_SMEM>>>(edge, We, be, Woe, boe, edge_out);
    softmax_kernel<<<BN, 256, SM_SMEM>>>(bon, node_out);
}

// round 3
// speedup vs baseline: 2.3322x; 2.3322x over previous
#include <cuda_runtime.h>
#include <cuda_bf16.h>
#include <math.h>
#include <stdint.h>

#define Bdim 16
#define Ndim 128
#define Cdim 256
#define BN   (Bdim*Ndim)            // 2048
#define INVS 0.1767766952966369f

// ---------------- device globals (allocation-free scratch) ----------------
__device__ float g_q[BN*Cdim];
__device__ float g_k[BN*Cdim];
__device__ float g_v[BN*Cdim];
__device__ float g_agg[BN*Cdim];
__device__ __nv_bfloat16 g_We_hi[Cdim*Cdim], g_We_lo[Cdim*Cdim];
__device__ __nv_bfloat16 g_Woe_hi[Cdim*Cdim], g_Woe_lo[Cdim*Cdim];

// ---------------- smem layout for edge kernel (byte offsets) ----------------
#define AHI   0          // edge hi  [128][264 bf16] stride 528B  = 67584
#define ALO   67584      // edge lo                              = 67584
#define SB    135168     // shared B / v staging buffer            36864
#define ATH   172032     // attn hi  [128][72 bf16] stride 144B  = 18432
#define ATL   190464     // attn lo                              = 18432
#define SQ_   208896     // q row (256 f32)
#define SBE_  209920     // be
#define SBOE_ 210944     // boe
#define ESMEM 211968

// ---------------- PTX helpers ----------------
__device__ __forceinline__ uint32_t smem_u32(const void* p) {
    uint32_t a;
    asm("{ .reg .u64 t; cvta.to.shared.u64 t, %1; cvt.u32.u64 %0, t; }" : "=r"(a) : "l"(p));
    return a;
}
__device__ __forceinline__ void ldm4(uint32_t addr, uint32_t r[4]) {
    asm volatile("ldmatrix.sync.aligned.m8n8.x4.shared.b16 {%0,%1,%2,%3}, [%4];"
                 : "=r"(r[0]), "=r"(r[1]), "=r"(r[2]), "=r"(r[3]) : "r"(addr));
}
__device__ __forceinline__ void mma_bf16(float d[4], const uint32_t a[4],
                                         uint32_t b0, uint32_t b1) {
    asm volatile("mma.sync.aligned.m16n8k16.row.col.f32.bf16.bf16.f32 "
                 "{%0,%1,%2,%3}, {%4,%5,%6,%7}, {%8,%9}, {%0,%1,%2,%3};"
                 : "+f"(d[0]), "+f"(d[1]), "+f"(d[2]), "+f"(d[3])
                 : "r"(a[0]), "r"(a[1]), "r"(a[2]), "r"(a[3]), "r"(b0), "r"(b1));
}
__device__ __forceinline__ uint32_t pk(float a, float b) {
    __nv_bfloat162 t = __floats2bfloat162_rn(a, b);
    return *reinterpret_cast<uint32_t*>(&t);
}
__device__ __forceinline__ float hf(float x) {
    return __bfloat162float(__float2bfloat16(x));
}

// ---------------- weight split prep ----------------
__global__ void prep_w(const float* __restrict__ We, const float* __restrict__ Woe) {
    int n = blockIdx.x, w = blockIdx.y, k = threadIdx.x;
    const float* W = w ? Woe : We;
    float x = W[n*Cdim + k];
    __nv_bfloat16 hi = __float2bfloat16(x);
    __nv_bfloat16 lo = __float2bfloat16(x - __bfloat162float(hi));
    if (w) { g_Woe_hi[n*Cdim+k] = hi; g_Woe_lo[n*Cdim+k] = lo; }
    else   { g_We_hi [n*Cdim+k] = hi; g_We_lo [n*Cdim+k] = lo; }
}

// ---------------- fp32 tile GEMM (qkv + node_out, small) ----------------
#define SASTR 36
#define SBSTR 260

__device__ __forceinline__ void load_tileA(float* sA, const float* __restrict__ X,
                                           int row0, int kc, int tid) {
    #pragma unroll
    for (int it = 0; it < 2; it++) {
        int idx = tid + it*256;
        int r = idx >> 3, k4 = idx & 7;
        float4 t = *(const float4*)(X + (size_t)(row0 + r)*Cdim + kc*32 + k4*4);
        *(float4*)(sA + r*SASTR + k4*4) = t;
    }
}
__device__ __forceinline__ void load_tileB(float* sB, const float* __restrict__ W,
                                           int kc, int tid) {
    #pragma unroll
    for (int it = 0; it < 8; it++) {
        int idx = tid + it*256;
        int c = idx >> 3, k4 = idx & 7;
        float4 t = *(const float4*)(W + c*Cdim + kc*32 + k4*4);
        sB[(k4*4+0)*SBSTR + c] = t.x;
        sB[(k4*4+1)*SBSTR + c] = t.y;
        sB[(k4*4+2)*SBSTR + c] = t.z;
        sB[(k4*4+3)*SBSTR + c] = t.w;
    }
}
__device__ __forceinline__ void mma_chunk_sA(const float* sA, const float* sB,
                                             float acc[8][8], int tx, int ty) {
    #pragma unroll
    for (int k = 0; k < 32; k++) {
        float a[8];
        #pragma unroll
        for (int mm = 0; mm < 4; mm++) {
            a[mm]   = sA[(ty*4+mm)*SASTR + k];
            a[4+mm] = sA[(32+ty*4+mm)*SASTR + k];
        }
        float4 p0 = *(const float4*)(sB + k*SBSTR + tx*4);
        float4 p1 = *(const float4*)(sB + k*SBSTR + 128 + tx*4);
        float bb[8] = {p0.x,p0.y,p0.z,p0.w,p1.x,p1.y,p1.z,p1.w};
        #pragma unroll
        for (int m = 0; m < 8; m++)
            #pragma unroll
            for (int n = 0; n < 8; n++)
                acc[m][n] = fmaf(a[m], bb[n], acc[m][n]);
    }
}

__global__ __launch_bounds__(256) void proj_kernel(
    const float* __restrict__ X,
    const float* __restrict__ W0, const float* __restrict__ b0,
    const float* __restrict__ W1, const float* __restrict__ b1,
    const float* __restrict__ W2, const float* __restrict__ b2)
{
    __shared__ float sA[64*SASTR];
    __shared__ float sB[32*SBSTR];
    int which = blockIdx.y;
    const float* W    = (which==0) ? W0 : (which==1 ? W1 : W2);
    const float* bias = (which==0) ? b0 : (which==1 ? b1 : b2);
    float* Y          = (which==0) ? g_q : (which==1 ? g_k : g_v);

    int tid = threadIdx.x;
    int tx = tid & 31, ty = tid >> 5;
    int row0 = blockIdx.x * 64;

    float acc[8][8];
    #pragma unroll
    for (int m = 0; m < 8; m++)
        #pragma unroll
        for (int n = 0; n < 8; n++) acc[m][n] = 0.f;

    for (int kc = 0; kc < 8; kc++) {
        __syncthreads();
        load_tileA(sA, X, row0, kc, tid);
        load_tileB(sB, W, kc, tid);
        __syncthreads();
        mma_chunk_sA(sA, sB, acc, tx, ty);
    }
    #pragma unroll
    for (int mh = 0; mh < 2; mh++)
    #pragma unroll
    for (int mm = 0; mm < 4; mm++) {
        int m = mh*4 + mm;
        int rloc = mh*32 + ty*4 + mm;
        size_t grow = (size_t)(row0 + rloc) * Cdim;
        #pragma unroll
        for (int nh = 0; nh < 2; nh++) {
            int col0 = nh*128 + tx*4;
            float4 o;
            o.x = acc[m][nh*4+0] + bias[col0+0];
            o.y = acc[m][nh*4+1] + bias[col0+1];
            o.z = acc[m][nh*4+2] + bias[col0+2];
            o.w = acc[m][nh*4+3] + bias[col0+3];
            *(float4*)(Y + grow + col0) = o;
        }
    }
}

__global__ __launch_bounds__(256) void node_final_kernel(
    const float* __restrict__ W, const float* __restrict__ bias,
    float* __restrict__ Y)
{
    __shared__ float sA[64*SASTR];
    __shared__ float sB[32*SBSTR];
    int tid = threadIdx.x;
    int tx = tid & 31, ty = tid >> 5;
    int row0 = blockIdx.x * 64;

    float acc[8][8];
    #pragma unroll
    for (int m = 0; m < 8; m++)
        #pragma unroll
        for (int n = 0; n < 8; n++) acc[m][n] = 0.f;

    for (int kc = 0; kc < 8; kc++) {
        __syncthreads();
        load_tileA(sA, g_agg, row0, kc, tid);
        load_tileB(sB, W, kc, tid);
        __syncthreads();
        mma_chunk_sA(sA, sB, acc, tx, ty);
    }
    #pragma unroll
    for (int mh = 0; mh < 2; mh++)
    #pragma unroll
    for (int mm = 0; mm < 4; mm++) {
        int m = mh*4 + mm;
        int rloc = mh*32 + ty*4 + mm;
        size_t grow = (size_t)(row0 + rloc) * Cdim;
        #pragma unroll
        for (int nh = 0; nh < 2; nh++) {
            int col0 = nh*128 + tx*4;
            float4 o;
            o.x = acc[m][nh*4+0] + bias[col0+0];
            o.y = acc[m][nh*4+1] + bias[col0+1];
            o.z = acc[m][nh*4+2] + bias[col0+2];
            o.w = acc[m][nh*4+3] + bias[col0+3];
            *(float4*)(Y + grow + col0) = o;
        }
    }
}

// ---------------- edge kernel: tile loads ----------------
__device__ __forceinline__ void loadB1(char* sm, const __nv_bfloat16* gW, int nc, int tid) {
    const uint4* src = (const uint4*)(gW + (size_t)nc*64*Cdim);
    #pragma unroll
    for (int it = 0; it < 4; it++) {
        int idx = tid + it*512;
        int row = idx >> 5, part = idx & 31;
        *(uint4*)(sm + SB + row*528 + part*16) = src[idx];
    }
}
__device__ __forceinline__ void loadB2(char* sm, const __nv_bfloat16* gW, int nc, int tid) {
    const uint4* src = (const uint4*)gW;
    #pragma unroll
    for (int it = 0; it < 4; it++) {
        int idx = tid + it*512;
        int row = idx >> 3, part = idx & 7;
        *(uint4*)(sm + SB + row*144 + part*16) = src[row*32 + nc*8 + part];
    }
}
__device__ __forceinline__ void loadVt(char* sm, int b, int nc, int tid) {
    const uint4* src = (const uint4*)(g_v + (size_t)b*Ndim*Cdim);
    #pragma unroll
    for (int it = 0; it < 4; it++) {
        int idx = tid + it*512;
        int row = idx >> 4, part = idx & 15;
        *(uint4*)(sm + SB + row*272 + part*16) = src[row*64 + nc*16 + part];
    }
}

// ---------------- edge GEMM passes ----------------
template<bool DUAL>
__device__ __forceinline__ void g1pass(uint32_t aHi, uint32_t aLo, uint32_t bB,
                                       float acc[4][4]) {
    uint32_t ah[4], al[4], bb[4];
    #pragma unroll
    for (int ks = 0; ks < 16; ks++) {
        ldm4(aHi + ks*32, ah);
        if (DUAL) ldm4(aLo + ks*32, al);
        #pragma unroll
        for (int ntp = 0; ntp < 2; ntp++) {
            ldm4(bB + ntp*(16*528) + ks*32, bb);
            mma_bf16(acc[ntp*2+0], ah, bb[0], bb[1]);
            mma_bf16(acc[ntp*2+1], ah, bb[2], bb[3]);
            if (DUAL) {
                mma_bf16(acc[ntp*2+0], al, bb[0], bb[1]);
                mma_bf16(acc[ntp*2+1], al, bb[2], bb[3]);
            }
        }
    }
}
template<bool DUAL>
__device__ __forceinline__ void g2pass(uint32_t aHi, uint32_t aLo, uint32_t bB,
                                       float acc[16][4]) {
    uint32_t ah[4], al[4], bb[4];
    #pragma unroll
    for (int ks = 0; ks < 4; ks++) {
        ldm4(aHi + ks*32, ah);
        if (DUAL) ldm4(aLo + ks*32, al);
        #pragma unroll
        for (int ntp = 0; ntp < 8; ntp++) {
            ldm4(bB + ntp*(16*144) + ks*32, bb);
            mma_bf16(acc[ntp*2+0], ah, bb[0], bb[1]);
            mma_bf16(acc[ntp*2+1], ah, bb[2], bb[3]);
            if (DUAL) {
                mma_bf16(acc[ntp*2+0], al, bb[0], bb[1]);
                mma_bf16(acc[ntp*2+1], al, bb[2], bb[3]);
            }
        }
    }
}

// ---------------- fused edge mega-kernel ----------------
__global__ __launch_bounds__(512, 1) void edge_fused(
    const float* __restrict__ edge,
    const float* __restrict__ be, const float* __restrict__ boe,
    float* __restrict__ edge_out)
{
    extern __shared__ char sm[];
    uint32_t sb = smem_u32(sm);
    const int tid  = threadIdx.x;
    const int lane = tid & 31, wid = tid >> 5;
    const int bi   = blockIdx.x;
    const int b    = bi >> 7;

    float* sQ   = (float*)(sm + SQ_);
    float* sBe  = (float*)(sm + SBE_);
    float* sBoe = (float*)(sm + SBOE_);
    if (tid < 256) {
        sQ[tid]   = g_q[(size_t)bi*Cdim + tid];
        sBe[tid]  = be[tid];
        sBoe[tid] = boe[tid];
    }

    // edge tile -> bf16 hi/lo in smem
    const float4* erow = (const float4*)(edge + (size_t)bi*(Ndim*Cdim));
    #pragma unroll
    for (int it = 0; it < 16; it++) {
        int idx = tid + it*512;
        float4 v = erow[idx];
        int j = idx >> 6, c4 = idx & 63;
        float hx = hf(v.x), hy = hf(v.y), hz = hf(v.z), hw = hf(v.w);
        uint2 uh, ul;
        uh.x = pk(v.x, v.y);        uh.y = pk(v.z, v.w);
        ul.x = pk(v.x-hx, v.y-hy);  ul.y = pk(v.z-hz, v.w-hw);
        *(uint2*)(sm + AHI + j*528 + c4*8) = uh;
        *(uint2*)(sm + ALO + j*528 + c4*8) = ul;
    }

    // fragment address offsets
    const int wm = wid & 7, wn = wid >> 3;
    const int m0 = wm*16;
    const uint32_t aoff  = (uint32_t)((m0 + (lane & 15))*528 + ((lane >> 4) << 4));
    const uint32_t atoff = (uint32_t)((m0 + (lane & 15))*144 + ((lane >> 4) << 4));
    const uint32_t b1off = (uint32_t)((wn*32  + (lane & 7) + ((lane & 16) ? 8 : 0))*528 + ((lane & 8) << 1));
    const uint32_t b2off = (uint32_t)((wn*128 + (lane & 7) + ((lane & 16) ? 8 : 0))*144 + ((lane & 8) << 1));

    float acc2[16][4];
    #pragma unroll
    for (int i = 0; i < 16; i++)
        #pragma unroll
        for (int r = 0; r < 4; r++) acc2[i][r] = 0.f;

    const int r0 = m0 + (lane >> 2);

    for (int nc = 0; nc < 4; nc++) {
        float acc1[4][4];
        #pragma unroll
        for (int i = 0; i < 4; i++)
            #pragma unroll
            for (int r = 0; r < 4; r++) acc1[i][r] = 0.f;

        __syncthreads();                           // prev readers of sB/sAttn done
        loadB1(sm, g_We_hi, nc, tid);  __syncthreads();
        g1pass<true>(sb + AHI + aoff, sb + ALO + aoff, sb + SB + b1off, acc1);
        __syncthreads();
        loadB1(sm, g_We_lo, nc, tid);  __syncthreads();
        g1pass<false>(sb + AHI + aoff, sb + ALO + aoff, sb + SB + b1off, acc1);

        // ---- gating epilogue -> attn hi/lo ----
        #pragma unroll
        for (int nt = 0; nt < 4; nt++) {
            int c_loc = wn*32 + nt*8 + ((lane & 3) << 1);
            int c = nc*64 + c_loc;
            float q0 = sQ[c], q1 = sQ[c+1];
            float be0 = sBe[c], be1 = sBe[c+1];
            float2 k0 = *(const float2*)(g_k + (size_t)(b*Ndim + r0)*Cdim + c);
            float2 k1 = *(const float2*)(g_k + (size_t)(b*Ndim + r0 + 8)*Cdim + c);
            float e00 = acc1[nt][0] + be0, e01 = acc1[nt][1] + be1;
            float e10 = acc1[nt][2] + be0, e11 = acc1[nt][3] + be1;
            float a00 = q0*k0.x*INVS*(e00*e00 + e00);
            float a01 = q1*k0.y*INVS*(e01*e01 + e01);
            float a10 = q0*k1.x*INVS*(e10*e10 + e10);
            float a11 = q1*k1.y*INVS*(e11*e11 + e11);
            *(uint32_t*)(sm + ATH + r0*144 + c_loc*2)     = pk(a00, a01);
            *(uint32_t*)(sm + ATL + r0*144 + c_loc*2)     = pk(a00 - hf(a00), a01 - hf(a01));
            *(uint32_t*)(sm + ATH + (r0+8)*144 + c_loc*2) = pk(a10, a11);
            *(uint32_t*)(sm + ATL + (r0+8)*144 + c_loc*2) = pk(a10 - hf(a10), a11 - hf(a11));
        }

        __syncthreads();                           // attn visible, sB free
        loadVt(sm, b, nc, tid);  __syncthreads();

        // ---- per-chunk softmax + v aggregation (full j present) ----
        {
            int c_loc = wid*4 + (lane >> 3);
            int lg = lane & 7;
            const __nv_bfloat16* pH = (const __nv_bfloat16*)(sm + ATH);
            const __nv_bfloat16* pL = (const __nv_bfloat16*)(sm + ATL);
            const float* sV = (const float*)(sm + SB);
            float val[16];
            float mx = -1e30f;
            #pragma unroll
            for (int t = 0; t < 16; t++) {
                int j = lg + t*8;
                float vv = __bfloat162float(pH[j*72 + c_loc]) +
                           __bfloat162float(pL[j*72 + c_loc]);
                val[t] = vv;
                mx = fmaxf(mx, vv);
            }
            mx = fmaxf(mx, __shfl_xor_sync(0xffffffffu, mx, 1));
            mx = fmaxf(mx, __shfl_xor_sync(0xffffffffu, mx, 2));
            mx = fmaxf(mx, __shfl_xor_sync(0xffffffffu, mx, 4));
            float s = 0.f, ag = 0.f;
            #pragma unroll
            for (int t = 0; t < 16; t++) {
                float p = __expf(val[t] - mx);
                s  += p;
                ag += p * sV[(lg + t*8)*68 + c_loc];
            }
            s  += __shfl_xor_sync(0xffffffffu, s, 1);
            ag += __shfl_xor_sync(0xffffffffu, ag, 1);
            s  += __shfl_xor_sync(0xffffffffu, s, 2);
            ag += __shfl_xor_sync(0xffffffffu, ag, 2);
            s  += __shfl_xor_sync(0xffffffffu, s, 4);
            ag += __shfl_xor_sync(0xffffffffu, ag, 4);
            if (lg == 0)
                g_agg[(size_t)bi*Cdim + nc*64 + c_loc] = ag / s;
        }

        __syncthreads();                           // sV reads done
        loadB2(sm, g_Woe_hi, nc, tid);  __syncthreads();
        g2pass<true>(sb + ATH + atoff, sb + ATL + atoff, sb + SB + b2off, acc2);
        __syncthreads();
        loadB2(sm, g_Woe_lo, nc, tid);  __syncthreads();
        g2pass<false>(sb + ATH + atoff, sb + ATL + atoff, sb + SB + b2off, acc2);
    }

    // ---- edge_out epilogue ----
    float* out0 = edge_out + ((size_t)bi*Ndim + r0)*Cdim;
    float* out1 = out0 + 8*Cdim;
    #pragma unroll
    for (int nt = 0; nt < 16; nt++) {
        int n = wn*128 + nt*8 + ((lane & 3) << 1);
        float2 o0, o1;
        o0.x = acc2[nt][0] + sBoe[n];   o0.y = acc2[nt][1] + sBoe[n+1];
        o1.x = acc2[nt][2] + sBoe[n];   o1.y = acc2[nt][3] + sBoe[n+1];
        *(float2*)(out0 + n) = o0;
        *(float2*)(out1 + n) = o1;
    }
}

// ---------------- launch ----------------
extern "C" void kernel_launch(void* const* d_in, const int* in_sizes, int n_in,
                              void* d_out, int out_size)
{
    const float* node = (const float*)d_in[0];
    const float* edge = (const float*)d_in[1];
    const float* Wq  = (const float*)d_in[2];  const float* bq  = (const float*)d_in[3];
    const float* Wk  = (const float*)d_in[4];  const float* bk  = (const float*)d_in[5];
    const float* Wv  = (const float*)d_in[6];  const float* bv  = (const float*)d_in[7];
    const float* We  = (const float*)d_in[8];  const float* be  = (const float*)d_in[9];
    const float* Woe = (const float*)d_in[10]; const float* boe = (const float*)d_in[11];
    const float* Won = (const float*)d_in[12]; const float* bon = (const float*)d_in[13];

    float* out = (float*)d_out;
    float* node_out = out;                       // [B,N,C]
    float* edge_out = out + (size_t)BN*Cdim;     // [B,N,N,C]

    cudaFuncSetAttribute(edge_fused, cudaFuncAttributeMaxDynamicSharedMemorySize, ESMEM);

    prep_w<<<dim3(Cdim, 2), Cdim>>>(We, Woe);
    proj_kernel<<<dim3(BN/64, 3), 256>>>(node, Wq, bq, Wk, bk, Wv, bv);
    edge_fused<<<BN, 512, ESMEM>>>(edge, be, boe, edge_out);
    node_final_kernel<<<BN/64, 256>>>(Won, bon, node_out);
}

// round 5
// speedup vs baseline: 2.9521x; 1.2658x over previous
#include <cuda_runtime.h>
#include <cuda_fp16.h>
#include <math.h>
#include <stdint.h>

#define Bdim 16
#define Ndim 128
#define Cdim 256
#define BN   2048
#define INVS 0.1767766952966369f

// ---------------- device globals ----------------
__device__ float g_q[BN*Cdim];
__device__ float g_k[BN*Cdim];
__device__ __align__(16) __half g_v16[BN*Cdim];
__device__ float g_WonT[Cdim*Cdim];
__device__ __align__(16) __half g_We_h[Cdim*Cdim], g_We_l[Cdim*Cdim];
__device__ __align__(16) __half g_Woe_h[Cdim*Cdim], g_Woe_l[Cdim*Cdim];

// ---------------- smem layout (bytes) ----------------
#define AHI   0          // edge fp16 [128][264h] stride 528   = 67584
#define ATH   67584      // attn fp16 [128][72h]  stride 144   = 18432
#define BB    86016      // B region: We hi/lo (+33792) or Woe hi/lo (+36864) = 73728
#define VB    159744     // v fp16 [128][264h] stride 528      = 67584
#define SQ_   227328
#define SBE_  228352
#define SBOE_ 229376
#define SAGG_ 230400
#define ESMEM 231424

// ---------------- PTX helpers ----------------
__device__ __forceinline__ uint32_t smem_u32(const void* p) {
    uint32_t a;
    asm("{ .reg .u64 t; cvta.to.shared.u64 t, %1; cvt.u32.u64 %0, t; }" : "=r"(a) : "l"(p));
    return a;
}
__device__ __forceinline__ void ldm4(uint32_t addr, uint32_t r[4]) {
    asm volatile("ldmatrix.sync.aligned.m8n8.x4.shared.b16 {%0,%1,%2,%3}, [%4];"
                 : "=r"(r[0]), "=r"(r[1]), "=r"(r[2]), "=r"(r[3]) : "r"(addr));
}
__device__ __forceinline__ void mma_f16(float d[4], const uint32_t a[4],
                                        uint32_t b0, uint32_t b1) {
    asm volatile("mma.sync.aligned.m16n8k16.row.col.f32.f16.f16.f32 "
                 "{%0,%1,%2,%3}, {%4,%5,%6,%7}, {%8,%9}, {%0,%1,%2,%3};"
                 : "+f"(d[0]), "+f"(d[1]), "+f"(d[2]), "+f"(d[3])
                 : "r"(a[0]), "r"(a[1]), "r"(a[2]), "r"(a[3]), "r"(b0), "r"(b1));
}
__device__ __forceinline__ uint32_t hpk(float a, float b) {
    __half2 t = __floats2half2_rn(a, b);
    return *reinterpret_cast<uint32_t*>(&t);
}
__device__ __forceinline__ void cp16(uint32_t d, const void* s) {
    asm volatile("cp.async.cg.shared.global [%0], [%1], 16;" :: "r"(d), "l"(s));
}
#define CP_COMMIT asm volatile("cp.async.commit_group;" ::: "memory")
#define CP_WAIT0  asm volatile("cp.async.wait_group 0;" ::: "memory")

// ---------------- weight prep ----------------
__global__ void prep_w(const float* __restrict__ We, const float* __restrict__ Woe,
                       const float* __restrict__ Won) {
    int n = blockIdx.x, w = blockIdx.y, k = threadIdx.x;
    if (w == 2) { g_WonT[k*Cdim + n] = Won[n*Cdim + k]; return; }
    const float* W = w ? Woe : We;
    float x = W[n*Cdim + k];
    __half hi = __float2half(x);
    __half lo = __float2half(x - __half2float(hi));
    if (w) { g_Woe_h[n*Cdim+k] = hi; g_Woe_l[n*Cdim+k] = lo; }
    else   { g_We_h [n*Cdim+k] = hi; g_We_l [n*Cdim+k] = lo; }
}

// ---------------- fp32 qkv projection ----------------
#define SASTR 36
#define SBSTR 260

__device__ __forceinline__ void load_tileA(float* sA, const float* __restrict__ X,
                                           int row0, int kc, int tid) {
    #pragma unroll
    for (int it = 0; it < 2; it++) {
        int idx = tid + it*256;
        int r = idx >> 3, k4 = idx & 7;
        float4 t = *(const float4*)(X + (size_t)(row0 + r)*Cdim + kc*32 + k4*4);
        *(float4*)(sA + r*SASTR + k4*4) = t;
    }
}
__device__ __forceinline__ void load_tileB(float* sB, const float* __restrict__ W,
                                           int kc, int tid) {
    #pragma unroll
    for (int it = 0; it < 8; it++) {
        int idx = tid + it*256;
        int c = idx >> 3, k4 = idx & 7;
        float4 t = *(const float4*)(W + c*Cdim + kc*32 + k4*4);
        sB[(k4*4+0)*SBSTR + c] = t.x;
        sB[(k4*4+1)*SBSTR + c] = t.y;
        sB[(k4*4+2)*SBSTR + c] = t.z;
        sB[(k4*4+3)*SBSTR + c] = t.w;
    }
}
__device__ __forceinline__ void mma_chunk_sA(const float* sA, const float* sB,
                                             float acc[8][8], int tx, int ty) {
    #pragma unroll
    for (int k = 0; k < 32; k++) {
        float a[8];
        #pragma unroll
        for (int mm = 0; mm < 4; mm++) {
            a[mm]   = sA[(ty*4+mm)*SASTR + k];
            a[4+mm] = sA[(32+ty*4+mm)*SASTR + k];
        }
        float4 p0 = *(const float4*)(sB + k*SBSTR + tx*4);
        float4 p1 = *(const float4*)(sB + k*SBSTR + 128 + tx*4);
        float bb[8] = {p0.x,p0.y,p0.z,p0.w,p1.x,p1.y,p1.z,p1.w};
        #pragma unroll
        for (int m = 0; m < 8; m++)
            #pragma unroll
            for (int n = 0; n < 8; n++)
                acc[m][n] = fmaf(a[m], bb[n], acc[m][n]);
    }
}

__global__ __launch_bounds__(256) void proj_kernel(
    const float* __restrict__ X,
    const float* __restrict__ W0, const float* __restrict__ b0,
    const float* __restrict__ W1, const float* __restrict__ b1,
    const float* __restrict__ W2, const float* __restrict__ b2)
{
    __shared__ float sA[64*SASTR];
    __shared__ float sB[32*SBSTR];
    int which = blockIdx.y;
    const float* W    = (which==0) ? W0 : (which==1 ? W1 : W2);
    const float* bias = (which==0) ? b0 : (which==1 ? b1 : b2);

    int tid = threadIdx.x;
    int tx = tid & 31, ty = tid >> 5;
    int row0 = blockIdx.x * 64;

    float acc[8][8];
    #pragma unroll
    for (int m = 0; m < 8; m++)
        #pragma unroll
        for (int n = 0; n < 8; n++) acc[m][n] = 0.f;

    for (int kc = 0; kc < 8; kc++) {
        __syncthreads();
        load_tileA(sA, X, row0, kc, tid);
        load_tileB(sB, W, kc, tid);
        __syncthreads();
        mma_chunk_sA(sA, sB, acc, tx, ty);
    }
    #pragma unroll
    for (int mh = 0; mh < 2; mh++)
    #pragma unroll
    for (int mm = 0; mm < 4; mm++) {
        int m = mh*4 + mm;
        int rloc = mh*32 + ty*4 + mm;
        size_t grow = (size_t)(row0 + rloc) * Cdim;
        #pragma unroll
        for (int nh = 0; nh < 2; nh++) {
            int col0 = nh*128 + tx*4;
            float4 o;
            o.x = acc[m][nh*4+0] + bias[col0+0];
            o.y = acc[m][nh*4+1] + bias[col0+1];
            o.z = acc[m][nh*4+2] + bias[col0+2];
            o.w = acc[m][nh*4+3] + bias[col0+3];
            if (which == 0)      *(float4*)(g_q + grow + col0) = o;
            else if (which == 1) *(float4*)(g_k + grow + col0) = o;
            else {
                __half2 h0 = __floats2half2_rn(o.x, o.y);
                __half2 h1 = __floats2half2_rn(o.z, o.w);
                uint2 u;
                u.x = *reinterpret_cast<uint32_t*>(&h0);
                u.y = *reinterpret_cast<uint32_t*>(&h1);
                *(uint2*)(g_v16 + grow + col0) = u;
            }
        }
    }
}

// ---------------- edge kernel cp.async loaders ----------------
__device__ __forceinline__ void loadWe(uint32_t sb, int nc, int tid) {
    const __half* sh = g_We_h + (size_t)nc*64*Cdim;
    const __half* sl = g_We_l + (size_t)nc*64*Cdim;
    #pragma unroll
    for (int it = 0; it < 4; it++) {
        int idx = tid + it*512;
        int row = idx >> 5, part = idx & 31;
        cp16(sb + BB         + row*528 + part*16, sh + row*Cdim + part*8);
        cp16(sb + BB + 33792 + row*528 + part*16, sl + row*Cdim + part*8);
    }
}
__device__ __forceinline__ void loadWoe(uint32_t sb, int nc, int tid) {
    #pragma unroll
    for (int it = 0; it < 4; it++) {
        int idx = tid + it*512;
        int row = idx >> 3, part = idx & 7;
        cp16(sb + BB         + row*144 + part*16, g_Woe_h + row*Cdim + nc*64 + part*8);
        cp16(sb + BB + 36864 + row*144 + part*16, g_Woe_l + row*Cdim + nc*64 + part*8);
    }
}
__device__ __forceinline__ void loadV(uint32_t sb, int b, int tid) {
    const __half* src = g_v16 + (size_t)b*Ndim*Cdim;
    #pragma unroll
    for (int it = 0; it < 8; it++) {          // 128 rows x 32 parts = 4096 cp16
        int idx = tid + it*512;
        int row = idx >> 5, part = idx & 31;
        cp16(sb + VB + row*528 + part*16, src + row*Cdim + part*8);
    }
}

// ---------------- GEMM passes (hi+lo B fused into one accumulator) ----------------
__device__ __forceinline__ void g1(uint32_t aA, uint32_t bH, uint32_t bL, float acc[4][4]) {
    uint32_t a[4], bh[4], bl[4];
    #pragma unroll
    for (int ks = 0; ks < 16; ks++) {
        ldm4(aA + ks*32, a);
        #pragma unroll
        for (int ntp = 0; ntp < 2; ntp++) {
            ldm4(bH + ntp*(16*528) + ks*32, bh);
            mma_f16(acc[ntp*2+0], a, bh[0], bh[1]);
            mma_f16(acc[ntp*2+1], a, bh[2], bh[3]);
            ldm4(bL + ntp*(16*528) + ks*32, bl);
            mma_f16(acc[ntp*2+0], a, bl[0], bl[1]);
            mma_f16(acc[ntp*2+1], a, bl[2], bl[3]);
        }
    }
}
__device__ __forceinline__ void g2(uint32_t aA, uint32_t bH, uint32_t bL, float acc[16][4]) {
    uint32_t a[4], bh[4], bl[4];
    #pragma unroll
    for (int ks = 0; ks < 4; ks++) {
        ldm4(aA + ks*32, a);
        #pragma unroll
        for (int ntp = 0; ntp < 8; ntp++) {
            ldm4(bH + ntp*(16*144) + ks*32, bh);
            mma_f16(acc[ntp*2+0], a, bh[0], bh[1]);
            mma_f16(acc[ntp*2+1], a, bh[2], bh[3]);
            ldm4(bL + ntp*(16*144) + ks*32, bl);
            mma_f16(acc[ntp*2+0], a, bl[0], bl[1]);
            mma_f16(acc[ntp*2+1], a, bl[2], bl[3]);
        }
    }
}

// ---------------- fused edge mega-kernel ----------------
__global__ __launch_bounds__(512, 1) void edge_fused(
    const float* __restrict__ edge,
    const float* __restrict__ be, const float* __restrict__ boe,
    const float* __restrict__ bon,
    float* __restrict__ edge_out, float* __restrict__ node_out)
{
    extern __shared__ char sm[];
    uint32_t sb = smem_u32(sm);
    const int tid  = threadIdx.x;
    const int lane = tid & 31, wid = tid >> 5;
    const int bi   = blockIdx.x;
    const int b    = bi >> 7;

    // prologue async loads (v tile + first We chunk)
    loadV(sb, b, tid);
    loadWe(sb, 0, tid);
    CP_COMMIT;

    float* sQ   = (float*)(sm + SQ_);
    float* sBe  = (float*)(sm + SBE_);
    float* sBoe = (float*)(sm + SBOE_);
    float* sAgg = (float*)(sm + SAGG_);
    if (tid < 256) {
        sQ[tid]   = g_q[(size_t)bi*Cdim + tid];
        sBe[tid]  = be[tid];
        sBoe[tid] = boe[tid];
    }

    // edge tile -> fp16 in smem
    const float4* erow = (const float4*)(edge + (size_t)bi*(Ndim*Cdim));
    #pragma unroll
    for (int it = 0; it < 16; it++) {
        int idx = tid + it*512;
        float4 v = erow[idx];
        int j = idx >> 6, c4 = idx & 63;
        __half2 h0 = __floats2half2_rn(v.x, v.y);
        __half2 h1 = __floats2half2_rn(v.z, v.w);
        uint2 u;
        u.x = *reinterpret_cast<uint32_t*>(&h0);
        u.y = *reinterpret_cast<uint32_t*>(&h1);
        *(uint2*)(sm + AHI + j*528 + c4*8) = u;
    }

    // fragment address offsets
    const int wm = wid & 7, wn = wid >> 3;
    const int m0 = wm*16;
    const uint32_t aoff  = (uint32_t)((m0 + (lane & 15))*528 + ((lane >> 4) << 4));
    const uint32_t atoff = (uint32_t)((m0 + (lane & 15))*144 + ((lane >> 4) << 4));
    const uint32_t b1off = (uint32_t)((wn*32  + (lane & 7) + ((lane & 16) ? 8 : 0))*528 + ((lane & 8) << 1));
    const uint32_t b2off = (uint32_t)((wn*128 + (lane & 7) + ((lane & 16) ? 8 : 0))*144 + ((lane & 8) << 1));

    float acc2[16][4];
    #pragma unroll
    for (int i = 0; i < 16; i++)
        #pragma unroll
        for (int r = 0; r < 4; r++) acc2[i][r] = 0.f;

    const int r0 = m0 + (lane >> 2);

    for (int nc = 0; nc < 4; nc++) {
        float acc1[4][4];
        #pragma unroll
        for (int i = 0; i < 4; i++)
            #pragma unroll
            for (int r = 0; r < 4; r++) acc1[i][r] = 0.f;

        CP_WAIT0; __syncthreads();                 // We(nc) (+V on nc=0) ready
        g1(sb + AHI + aoff, sb + BB + b1off, sb + BB + 33792 + b1off, acc1);
        __syncthreads();                           // BB reads done
        loadWoe(sb, nc, tid); CP_COMMIT;           // prefetch Woe during epilogue

        // ---- gating epilogue -> attn fp16 ----
        #pragma unroll
        for (int nt = 0; nt < 4; nt++) {
            int c_loc = wn*32 + nt*8 + ((lane & 3) << 1);
            int c = nc*64 + c_loc;
            float q0 = sQ[c], q1 = sQ[c+1];
            float be0 = sBe[c], be1 = sBe[c+1];
            float2 k0 = *(const float2*)(g_k + (size_t)(b*Ndim + r0)*Cdim + c);
            float2 k1 = *(const float2*)(g_k + (size_t)(b*Ndim + r0 + 8)*Cdim + c);
            float e00 = acc1[nt][0] + be0, e01 = acc1[nt][1] + be1;
            float e10 = acc1[nt][2] + be0, e11 = acc1[nt][3] + be1;
            float a00 = q0*k0.x*INVS*(e00*e00 + e00);
            float a01 = q1*k0.y*INVS*(e01*e01 + e01);
            float a10 = q0*k1.x*INVS*(e10*e10 + e10);
            float a11 = q1*k1.y*INVS*(e11*e11 + e11);
            *(uint32_t*)(sm + ATH + r0*144 + c_loc*2)     = hpk(a00, a01);
            *(uint32_t*)(sm + ATH + (r0+8)*144 + c_loc*2) = hpk(a10, a11);
        }

        CP_WAIT0; __syncthreads();                 // Woe ready + attn visible
        g2(sb + ATH + atoff, sb + BB + b2off, sb + BB + 36864 + b2off, acc2);
        __syncthreads();                           // BB reads done
        if (nc < 3) { loadWe(sb, nc+1, tid); CP_COMMIT; }   // overlaps softmax

        // ---- per-chunk softmax + v aggregation ----
        {
            int c_loc = wid*4 + (lane >> 3);
            int lg = lane & 7;
            const __half* pH = (const __half*)(sm + ATH);
            const __half* sV = (const __half*)(sm + VB);
            float val[16];
            float mx = -1e30f;
            #pragma unroll
            for (int t = 0; t < 16; t++) {
                float vv = __half2float(pH[(lg + t*8)*72 + c_loc]);
                val[t] = vv;
                mx = fmaxf(mx, vv);
            }
            mx = fmaxf(mx, __shfl_xor_sync(0xffffffffu, mx, 1));
            mx = fmaxf(mx, __shfl_xor_sync(0xffffffffu, mx, 2));
            mx = fmaxf(mx, __shfl_xor_sync(0xffffffffu, mx, 4));
            float s = 0.f, ag = 0.f;
            #pragma unroll
            for (int t = 0; t < 16; t++) {
                float p = __expf(val[t] - mx);
                s  += p;
                ag += p * __half2float(sV[(lg + t*8)*264 + nc*64 + c_loc]);
            }
            s  += __shfl_xor_sync(0xffffffffu, s, 1);
            ag += __shfl_xor_sync(0xffffffffu, ag, 1);
            s  += __shfl_xor_sync(0xffffffffu, s, 2);
            ag += __shfl_xor_sync(0xffffffffu, ag, 2);
            s  += __shfl_xor_sync(0xffffffffu, s, 4);
            ag += __shfl_xor_sync(0xffffffffu, ag, 4);
            if (lg == 0)
                sAgg[nc*64 + c_loc] = ag / s;
        }
    }

    // ---- edge_out epilogue ----
    {
        float* out0 = edge_out + ((size_t)bi*Ndim + r0)*Cdim;
        float* out1 = out0 + 8*Cdim;
        #pragma unroll
        for (int nt = 0; nt < 16; nt++) {
            int n = wn*128 + nt*8 + ((lane & 3) << 1);
            float2 o0, o1;
            o0.x = acc2[nt][0] + sBoe[n];   o0.y = acc2[nt][1] + sBoe[n+1];
            o1.x = acc2[nt][2] + sBoe[n];   o1.y = acc2[nt][3] + sBoe[n+1];
            *(float2*)(out0 + n) = o0;
            *(float2*)(out1 + n) = o1;
        }
    }

    // ---- node_out = agg @ Won^T + bon ----
    __syncthreads();
    {
        int c = tid & 255, half = tid >> 8;
        const float* wT = g_WonT + (size_t)(half*128)*Cdim + c;
        float s = 0.f;
        #pragma unroll 8
        for (int k = 0; k < 128; k++)
            s = fmaf(sAgg[half*128 + k], wT[(size_t)k*Cdim], s);
        float* sPart = (float*)(sm + VB);
        sPart[tid] = s;
        __syncthreads();
        if (tid < 256)
            node_out[(size_t)bi*Cdim + tid] = sPart[tid] + sPart[tid + 256] + bon[tid];
    }
}

// ---------------- launch ----------------
extern "C" void kernel_launch(void* const* d_in, const int* in_sizes, int n_in,
                              void* d_out, int out_size)
{
    const float* node = (const float*)d_in[0];
    const float* edge = (const float*)d_in[1];
    const float* Wq  = (const float*)d_in[2];  const float* bq  = (const float*)d_in[3];
    const float* Wk  = (const float*)d_in[4];  const float* bk  = (const float*)d_in[5];
    const float* Wv  = (const float*)d_in[6];  const float* bv  = (const float*)d_in[7];
    const float* We  = (const float*)d_in[8];  const float* be  = (const float*)d_in[9];
    const float* Woe = (const float*)d_in[10]; const float* boe = (const float*)d_in[11];
    const float* Won = (const float*)d_in[12]; const float* bon = (const float*)d_in[13];

    float* out = (float*)d_out;
    float* node_out = out;                       // [B,N,C]
    float* edge_out = out + (size_t)BN*Cdim;     // [B,N,N,C]

    cudaFuncSetAttribute(edge_fused, cudaFuncAttributeMaxDynamicSharedMemorySize, ESMEM);

    prep_w<<<dim3(Cdim, 3), Cdim>>>(We, Woe, Won);
    proj_kernel<<<dim3(BN/64, 3), 256>>>(node, Wq, bq, Wk, bk, Wv, bv);
    edge_fused<<<BN, 512, ESMEM>>>(edge, be, boe, bon, edge_out, node_out);
}

// round 6
// speedup vs baseline: 3.9368x; 1.3335x over previous
#include <cuda_runtime.h>
#include <cuda_fp16.h>
#include <math.h>
#include <stdint.h>

#define Bdim 16
#define Ndim 128
#define Cdim 256
#define BN   2048
#define INVS 0.1767766952966369f

// ---------------- device globals ----------------
__device__ float g_q[BN*Cdim];
__device__ float g_k[BN*Cdim];
__device__ __align__(16) __half g_v16[BN*Cdim];
__device__ float g_WonT[Cdim*Cdim];
__device__ __align__(16) __half g_We_h[Cdim*Cdim];
__device__ __align__(16) __half g_Woe_h[Cdim*Cdim];

// ---------------- smem layout (bytes) ----------------
#define AHI   0          // edge fp16 [128][264h] stride 528   = 67584
#define ATH   67584      // attn fp16 [128][72h]  stride 144   = 18432
#define BWE   86016      // We chunk  [64][264h]  stride 528   = 33792
#define BWO   119808     // Woe chunk [256][72h]  stride 144   = 36864
#define VB    159744     // v fp16 [128][264h] stride 528      = 67584
#define SQ_   227328
#define SBE_  228352
#define SBOE_ 229376
#define SAGG_ 230400
#define ESMEM 231424

// ---------------- PTX helpers ----------------
__device__ __forceinline__ uint32_t smem_u32(const void* p) {
    uint32_t a;
    asm("{ .reg .u64 t; cvta.to.shared.u64 t, %1; cvt.u32.u64 %0, t; }" : "=r"(a) : "l"(p));
    return a;
}
__device__ __forceinline__ void ldm4(uint32_t addr, uint32_t r[4]) {
    asm volatile("ldmatrix.sync.aligned.m8n8.x4.shared.b16 {%0,%1,%2,%3}, [%4];"
                 : "=r"(r[0]), "=r"(r[1]), "=r"(r[2]), "=r"(r[3]) : "r"(addr));
}
__device__ __forceinline__ void mma_f16(float d[4], const uint32_t a[4],
                                        uint32_t b0, uint32_t b1) {
    asm volatile("mma.sync.aligned.m16n8k16.row.col.f32.f16.f16.f32 "
                 "{%0,%1,%2,%3}, {%4,%5,%6,%7}, {%8,%9}, {%0,%1,%2,%3};"
                 : "+f"(d[0]), "+f"(d[1]), "+f"(d[2]), "+f"(d[3])
                 : "r"(a[0]), "r"(a[1]), "r"(a[2]), "r"(a[3]), "r"(b0), "r"(b1));
}
__device__ __forceinline__ uint32_t hpk(float a, float b) {
    __half2 t = __floats2half2_rn(a, b);
    return *reinterpret_cast<uint32_t*>(&t);
}
__device__ __forceinline__ void cp16(uint32_t d, const void* s) {
    asm volatile("cp.async.cg.shared.global [%0], [%1], 16;" :: "r"(d), "l"(s));
}
#define CP_COMMIT asm volatile("cp.async.commit_group;" ::: "memory")
#define CP_WAIT0  asm volatile("cp.async.wait_group 0;" ::: "memory")
#define CP_WAIT1  asm volatile("cp.async.wait_group 1;" ::: "memory")

// ---------------- weight prep ----------------
__global__ void prep_w(const float* __restrict__ We, const float* __restrict__ Woe,
                       const float* __restrict__ Won) {
    int n = blockIdx.x, w = blockIdx.y, k = threadIdx.x;
    if (w == 2) { g_WonT[k*Cdim + n] = Won[n*Cdim + k]; return; }
    const float* W = w ? Woe : We;
    __half hi = __float2half(W[n*Cdim + k]);
    if (w) g_Woe_h[n*Cdim+k] = hi;
    else   g_We_h [n*Cdim+k] = hi;
}

// ---------------- fp32 qkv projection ----------------
#define SASTR 36
#define SBSTR 260

__device__ __forceinline__ void load_tileA(float* sA, const float* __restrict__ X,
                                           int row0, int kc, int tid) {
    #pragma unroll
    for (int it = 0; it < 2; it++) {
        int idx = tid + it*256;
        int r = idx >> 3, k4 = idx & 7;
        float4 t = *(const float4*)(X + (size_t)(row0 + r)*Cdim + kc*32 + k4*4);
        *(float4*)(sA + r*SASTR + k4*4) = t;
    }
}
__device__ __forceinline__ void load_tileB(float* sB, const float* __restrict__ W,
                                           int kc, int tid) {
    #pragma unroll
    for (int it = 0; it < 8; it++) {
        int idx = tid + it*256;
        int c = idx >> 3, k4 = idx & 7;
        float4 t = *(const float4*)(W + c*Cdim + kc*32 + k4*4);
        sB[(k4*4+0)*SBSTR + c] = t.x;
        sB[(k4*4+1)*SBSTR + c] = t.y;
        sB[(k4*4+2)*SBSTR + c] = t.z;
        sB[(k4*4+3)*SBSTR + c] = t.w;
    }
}
__device__ __forceinline__ void mma_chunk_sA(const float* sA, const float* sB,
                                             float acc[8][8], int tx, int ty) {
    #pragma unroll
    for (int k = 0; k < 32; k++) {
        float a[8];
        #pragma unroll
        for (int mm = 0; mm < 4; mm++) {
            a[mm]   = sA[(ty*4+mm)*SASTR + k];
            a[4+mm] = sA[(32+ty*4+mm)*SASTR + k];
        }
        float4 p0 = *(const float4*)(sB + k*SBSTR + tx*4);
        float4 p1 = *(const float4*)(sB + k*SBSTR + 128 + tx*4);
        float bb[8] = {p0.x,p0.y,p0.z,p0.w,p1.x,p1.y,p1.z,p1.w};
        #pragma unroll
        for (int m = 0; m < 8; m++)
            #pragma unroll
            for (int n = 0; n < 8; n++)
                acc[m][n] = fmaf(a[m], bb[n], acc[m][n]);
    }
}

__global__ __launch_bounds__(256) void proj_kernel(
    const float* __restrict__ X,
    const float* __restrict__ W0, const float* __restrict__ b0,
    const float* __restrict__ W1, const float* __restrict__ b1,
    const float* __restrict__ W2, const float* __restrict__ b2)
{
    __shared__ float sA[64*SASTR];
    __shared__ float sB[32*SBSTR];
    int which = blockIdx.y;
    const float* W    = (which==0) ? W0 : (which==1 ? W1 : W2);
    const float* bias = (which==0) ? b0 : (which==1 ? b1 : b2);

    int tid = threadIdx.x;
    int tx = tid & 31, ty = tid >> 5;
    int row0 = blockIdx.x * 64;

    float acc[8][8];
    #pragma unroll
    for (int m = 0; m < 8; m++)
        #pragma unroll
        for (int n = 0; n < 8; n++) acc[m][n] = 0.f;

    for (int kc = 0; kc < 8; kc++) {
        __syncthreads();
        load_tileA(sA, X, row0, kc, tid);
        load_tileB(sB, W, kc, tid);
        __syncthreads();
        mma_chunk_sA(sA, sB, acc, tx, ty);
    }
    #pragma unroll
    for (int mh = 0; mh < 2; mh++)
    #pragma unroll
    for (int mm = 0; mm < 4; mm++) {
        int m = mh*4 + mm;
        int rloc = mh*32 + ty*4 + mm;
        size_t grow = (size_t)(row0 + rloc) * Cdim;
        #pragma unroll
        for (int nh = 0; nh < 2; nh++) {
            int col0 = nh*128 + tx*4;
            float4 o;
            o.x = acc[m][nh*4+0] + bias[col0+0];
            o.y = acc[m][nh*4+1] + bias[col0+1];
            o.z = acc[m][nh*4+2] + bias[col0+2];
            o.w = acc[m][nh*4+3] + bias[col0+3];
            if (which == 0)      *(float4*)(g_q + grow + col0) = o;
            else if (which == 1) *(float4*)(g_k + grow + col0) = o;
            else {
                __half2 h0 = __floats2half2_rn(o.x, o.y);
                __half2 h1 = __floats2half2_rn(o.z, o.w);
                uint2 u;
                u.x = *reinterpret_cast<uint32_t*>(&h0);
                u.y = *reinterpret_cast<uint32_t*>(&h1);
                *(uint2*)(g_v16 + grow + col0) = u;
            }
        }
    }
}

// ---------------- edge kernel cp.async loaders ----------------
__device__ __forceinline__ void loadWe(uint32_t sb, int nc, int tid) {
    const __half* sh = g_We_h + (size_t)nc*64*Cdim;
    #pragma unroll
    for (int it = 0; it < 4; it++) {
        int idx = tid + it*512;                 // 64 rows x 32 parts
        int row = idx >> 5, part = idx & 31;
        cp16(sb + BWE + row*528 + part*16, sh + row*Cdim + part*8);
    }
}
__device__ __forceinline__ void loadWoe(uint32_t sb, int nc, int tid) {
    #pragma unroll
    for (int it = 0; it < 4; it++) {
        int idx = tid + it*512;                 // 256 rows x 8 parts
        int row = idx >> 3, part = idx & 7;
        cp16(sb + BWO + row*144 + part*16, g_Woe_h + row*Cdim + nc*64 + part*8);
    }
}
__device__ __forceinline__ void loadV(uint32_t sb, int b, int tid) {
    const __half* src = g_v16 + (size_t)b*Ndim*Cdim;
    #pragma unroll
    for (int it = 0; it < 8; it++) {            // 128 rows x 32 parts
        int idx = tid + it*512;
        int row = idx >> 5, part = idx & 31;
        cp16(sb + VB + row*528 + part*16, src + row*Cdim + part*8);
    }
}

// ---------------- GEMM passes ----------------
__device__ __forceinline__ void g1(uint32_t aA, uint32_t bH, float acc[4][4]) {
    uint32_t a[4], bh[4];
    #pragma unroll
    for (int ks = 0; ks < 16; ks++) {
        ldm4(aA + ks*32, a);
        #pragma unroll
        for (int ntp = 0; ntp < 2; ntp++) {
            ldm4(bH + ntp*(16*528) + ks*32, bh);
            mma_f16(acc[ntp*2+0], a, bh[0], bh[1]);
            mma_f16(acc[ntp*2+1], a, bh[2], bh[3]);
        }
    }
}
__device__ __forceinline__ void g2(uint32_t aA, uint32_t bH, float acc[16][4]) {
    uint32_t a[4], bh[4];
    #pragma unroll
    for (int ks = 0; ks < 4; ks++) {
        ldm4(aA + ks*32, a);
        #pragma unroll
        for (int ntp = 0; ntp < 8; ntp++) {
            ldm4(bH + ntp*(16*144) + ks*32, bh);
            mma_f16(acc[ntp*2+0], a, bh[0], bh[1]);
            mma_f16(acc[ntp*2+1], a, bh[2], bh[3]);
        }
    }
}

// ---------------- fused edge mega-kernel ----------------
__global__ __launch_bounds__(512, 1) void edge_fused(
    const float* __restrict__ edge,
    const float* __restrict__ be, const float* __restrict__ boe,
    const float* __restrict__ bon,
    float* __restrict__ edge_out, float* __restrict__ node_out)
{
    extern __shared__ char sm[];
    uint32_t sb = smem_u32(sm);
    const int tid  = threadIdx.x;
    const int lane = tid & 31, wid = tid >> 5;
    const int bi   = blockIdx.x;
    const int b    = bi >> 7;

    // prologue: v tile + We0 (group A), Woe0 (group B)
    loadV(sb, b, tid);
    loadWe(sb, 0, tid);
    CP_COMMIT;
    loadWoe(sb, 0, tid);
    CP_COMMIT;

    float* sQ   = (float*)(sm + SQ_);
    float* sBe  = (float*)(sm + SBE_);
    float* sBoe = (float*)(sm + SBOE_);
    float* sAgg = (float*)(sm + SAGG_);
    if (tid < 256) {
        sQ[tid]   = g_q[(size_t)bi*Cdim + tid];
        sBe[tid]  = be[tid];
        sBoe[tid] = boe[tid];
    }

    // edge tile -> fp16 in smem
    const float4* erow = (const float4*)(edge + (size_t)bi*(Ndim*Cdim));
    #pragma unroll
    for (int it = 0; it < 16; it++) {
        int idx = tid + it*512;
        float4 v = erow[idx];
        int j = idx >> 6, c4 = idx & 63;
        __half2 h0 = __floats2half2_rn(v.x, v.y);
        __half2 h1 = __floats2half2_rn(v.z, v.w);
        uint2 u;
        u.x = *reinterpret_cast<uint32_t*>(&h0);
        u.y = *reinterpret_cast<uint32_t*>(&h1);
        *(uint2*)(sm + AHI + j*528 + c4*8) = u;
    }

    // fragment address offsets
    const int wm = wid & 7, wn = wid >> 3;
    const int m0 = wm*16;
    const uint32_t aoff  = (uint32_t)((m0 + (lane & 15))*528 + ((lane >> 4) << 4));
    const uint32_t atoff = (uint32_t)((m0 + (lane & 15))*144 + ((lane >> 4) << 4));
    const uint32_t b1off = (uint32_t)((wn*32  + (lane & 7) + ((lane & 16) ? 8 : 0))*528 + ((lane & 8) << 1));
    const uint32_t b2off = (uint32_t)((wn*128 + (lane & 7) + ((lane & 16) ? 8 : 0))*144 + ((lane & 8) << 1));

    float acc2[16][4];
    #pragma unroll
    for (int i = 0; i < 16; i++)
        #pragma unroll
        for (int r = 0; r < 4; r++) acc2[i][r] = 0.f;

    const int r0 = m0 + (lane >> 2);

    for (int nc = 0; nc < 4; nc++) {
        float acc1[4][4];
        #pragma unroll
        for (int i = 0; i < 4; i++)
            #pragma unroll
            for (int r = 0; r < 4; r++) acc1[i][r] = 0.f;

        CP_WAIT1; __syncthreads();                 // We(nc) (+V on nc=0) ready; Woe(nc) may be in flight
        g1(sb + AHI + aoff, sb + BWE + b1off, acc1);
        __syncthreads();                           // all warps done reading We buffer
        if (nc < 3) { loadWe(sb, nc+1, tid); CP_COMMIT; }

        // ---- gating epilogue -> attn fp16 ----
        #pragma unroll
        for (int nt = 0; nt < 4; nt++) {
            int c_loc = wn*32 + nt*8 + ((lane & 3) << 1);
            int c = nc*64 + c_loc;
            float q0 = sQ[c], q1 = sQ[c+1];
            float be0 = sBe[c], be1 = sBe[c+1];
            float2 k0 = *(const float2*)(g_k + (size_t)(b*Ndim + r0)*Cdim + c);
            float2 k1 = *(const float2*)(g_k + (size_t)(b*Ndim + r0 + 8)*Cdim + c);
            float e00 = acc1[nt][0] + be0, e01 = acc1[nt][1] + be1;
            float e10 = acc1[nt][2] + be0, e11 = acc1[nt][3] + be1;
            float a00 = q0*k0.x*INVS*(e00*e00 + e00);
            float a01 = q1*k0.y*INVS*(e01*e01 + e01);
            float a10 = q0*k1.x*INVS*(e10*e10 + e10);
            float a11 = q1*k1.y*INVS*(e11*e11 + e11);
            *(uint32_t*)(sm + ATH + r0*144 + c_loc*2)     = hpk(a00, a01);
            *(uint32_t*)(sm + ATH + (r0+8)*144 + c_loc*2) = hpk(a10, a11);
        }

        if (nc < 3) { CP_WAIT1; } else { CP_WAIT0; }   // Woe(nc) ready
        __syncthreads();                               // attn visible
        g2(sb + ATH + atoff, sb + BWO + b2off, acc2);
        __syncthreads();                               // Woe buffer + ATH reads done
        if (nc < 3) { loadWoe(sb, nc+1, tid); CP_COMMIT; }

        // ---- per-chunk softmax + v aggregation (overlaps Woe prefetch) ----
        {
            int c_loc = wid*4 + (lane >> 3);
            int lg = lane & 7;
            const __half* pH = (const __half*)(sm + ATH);
            const __half* sV = (const __half*)(sm + VB);
            float val[16];
            float mx = -1e30f;
            #pragma unroll
            for (int t = 0; t < 16; t++) {
                float vv = __half2float(pH[(lg + t*8)*72 + c_loc]);
                val[t] = vv;
                mx = fmaxf(mx, vv);
            }
            mx = fmaxf(mx, __shfl_xor_sync(0xffffffffu, mx, 1));
            mx = fmaxf(mx, __shfl_xor_sync(0xffffffffu, mx, 2));
            mx = fmaxf(mx, __shfl_xor_sync(0xffffffffu, mx, 4));
            float s = 0.f, ag = 0.f;
            #pragma unroll
            for (int t = 0; t < 16; t++) {
                float p = __expf(val[t] - mx);
                s  += p;
                ag += p * __half2float(sV[(lg + t*8)*264 + nc*64 + c_loc]);
            }
            s  += __shfl_xor_sync(0xffffffffu, s, 1);
            ag += __shfl_xor_sync(0xffffffffu, ag, 1);
            s  += __shfl_xor_sync(0xffffffffu, s, 2);
            ag += __shfl_xor_sync(0xffffffffu, ag, 2);
            s  += __shfl_xor_sync(0xffffffffu, s, 4);
            ag += __shfl_xor_sync(0xffffffffu, ag, 4);
            if (lg == 0)
                sAgg[nc*64 + c_loc] = ag / s;
        }
    }

    // ---- edge_out epilogue ----
    {
        float* out0 = edge_out + ((size_t)bi*Ndim + r0)*Cdim;
        float* out1 = out0 + 8*Cdim;
        #pragma unroll
        for (int nt = 0; nt < 16; nt++) {
            int n = wn*128 + nt*8 + ((lane & 3) << 1);
            float2 o0, o1;
            o0.x = acc2[nt][0] + sBoe[n];   o0.y = acc2[nt][1] + sBoe[n+1];
            o1.x = acc2[nt][2] + sBoe[n];   o1.y = acc2[nt][3] + sBoe[n+1];
            *(float2*)(out0 + n) = o0;
            *(float2*)(out1 + n) = o1;
        }
    }

    // ---- node_out = agg @ Won^T + bon ----
    __syncthreads();
    {
        int c = tid & 255, half = tid >> 8;
        const float* wT = g_WonT + (size_t)(half*128)*Cdim + c;
        float s = 0.f;
        #pragma unroll 8
        for (int k = 0; k < 128; k++)
            s = fmaf(sAgg[half*128 + k], wT[(size_t)k*Cdim], s);
        float* sPart = (float*)(sm + VB);
        sPart[tid] = s;
        __syncthreads();
        if (tid < 256)
            node_out[(size_t)bi*Cdim + tid] = sPart[tid] + sPart[tid + 256] + bon[tid];
    }
}

// ---------------- launch ----------------
extern "C" void kernel_launch(void* const* d_in, const int* in_sizes, int n_in,
                              void* d_out, int out_size)
{
    const float* node = (const float*)d_in[0];
    const float* edge = (const float*)d_in[1];
    const float* Wq  = (const float*)d_in[2];  const float* bq  = (const float*)d_in[3];
    const float* Wk  = (const float*)d_in[4];  const float* bk  = (const float*)d_in[5];
    const float* Wv  = (const float*)d_in[6];  const float* bv  = (const float*)d_in[7];
    const float* We  = (const float*)d_in[8];  const float* be  = (const float*)d_in[9];
    const float* Woe = (const float*)d_in[10]; const float* boe = (const float*)d_in[11];
    const float* Won = (const float*)d_in[12]; const float* bon = (const float*)d_in[13];

    float* out = (float*)d_out;
    float* node_out = out;                       // [B,N,C]
    float* edge_out = out + (size_t)BN*Cdim;     // [B,N,N,C]

    cudaFuncSetAttribute(edge_fused, cudaFuncAttributeMaxDynamicSharedMemorySize, ESMEM);

    prep_w<<<dim3(Cdim, 3), Cdim>>>(We, Woe, Won);
    proj_kernel<<<dim3(BN/64, 3), 256>>>(node, Wq, bq, Wk, bk, Wv, bv);
    edge_fused<<<BN, 512, ESMEM>>>(edge, be, boe, bon, edge_out, node_out);
}

// round 7
// speedup vs baseline: 4.0380x; 1.0257x over previous
#include <cuda_runtime.h>
#include <cuda_fp16.h>
#include <math.h>
#include <stdint.h>

#define Bdim 16
#define Ndim 128
#define Cdim 256
#define BN   2048
#define INVS 0.1767766952966369f

// ---------------- device globals ----------------
__device__ float g_q[BN*Cdim];
__device__ float g_k[BN*Cdim];
__device__ __align__(16) __half g_v16[BN*Cdim];
__device__ float g_WonT[Cdim*Cdim];
__device__ __align__(16) __half g_We_h[Cdim*Cdim];
__device__ __align__(16) __half g_Woe_h[Cdim*Cdim];
__device__ float g_ps [2*BN*Cdim];   // softmax partial sums
__device__ float g_pag[2*BN*Cdim];   // weighted-v partial sums
__device__ int   g_cnt[BN];          // zero-init; self-resetting per launch

// ---------------- smem layout (bytes) ----------------
#define EDG   0        // edge fp16 [64][264h] stride 528      = 33792
#define ATT   33792    // attn fp16 4 chunks x [64][72h] s144  = 36864
#define WB    70656    // weight buf: We chunk or Woe chunk    = 36864
#define SQ_   107520
#define SBE_  108544
#define SBOE_ 109568
#define SAGG_ 110592
#define ESMEM 111616

// ---------------- PTX helpers ----------------
__device__ __forceinline__ uint32_t smem_u32(const void* p) {
    uint32_t a;
    asm("{ .reg .u64 t; cvta.to.shared.u64 t, %1; cvt.u32.u64 %0, t; }" : "=r"(a) : "l"(p));
    return a;
}
__device__ __forceinline__ void ldm4(uint32_t addr, uint32_t r[4]) {
    asm volatile("ldmatrix.sync.aligned.m8n8.x4.shared.b16 {%0,%1,%2,%3}, [%4];"
                 : "=r"(r[0]), "=r"(r[1]), "=r"(r[2]), "=r"(r[3]) : "r"(addr));
}
__device__ __forceinline__ void mma_f16(float d[4], const uint32_t a[4],
                                        uint32_t b0, uint32_t b1) {
    asm volatile("mma.sync.aligned.m16n8k16.row.col.f32.f16.f16.f32 "
                 "{%0,%1,%2,%3}, {%4,%5,%6,%7}, {%8,%9}, {%0,%1,%2,%3};"
                 : "+f"(d[0]), "+f"(d[1]), "+f"(d[2]), "+f"(d[3])
                 : "r"(a[0]), "r"(a[1]), "r"(a[2]), "r"(a[3]), "r"(b0), "r"(b1));
}
__device__ __forceinline__ uint32_t hpk(float a, float b) {
    __half2 t = __floats2half2_rn(a, b);
    return *reinterpret_cast<uint32_t*>(&t);
}
__device__ __forceinline__ void cp16(uint32_t d, const void* s) {
    asm volatile("cp.async.cg.shared.global [%0], [%1], 16;" :: "r"(d), "l"(s));
}
#define CP_COMMIT asm volatile("cp.async.commit_group;" ::: "memory")
#define CP_WAIT0  asm volatile("cp.async.wait_group 0;" ::: "memory")

// ---------------- weight prep ----------------
__global__ void prep_w(const float* __restrict__ We, const float* __restrict__ Woe,
                       const float* __restrict__ Won) {
    int n = blockIdx.x, w = blockIdx.y, k = threadIdx.x;
    if (w == 2) { g_WonT[k*Cdim + n] = Won[n*Cdim + k]; return; }
    const float* W = w ? Woe : We;
    __half hi = __float2half(W[n*Cdim + k]);
    if (w) g_Woe_h[n*Cdim+k] = hi;
    else   g_We_h [n*Cdim+k] = hi;
}

// ---------------- fp32 qkv projection ----------------
#define SASTR 36
#define SBSTR 260

__device__ __forceinline__ void load_tileA(float* sA, const float* __restrict__ X,
                                           int row0, int kc, int tid) {
    #pragma unroll
    for (int it = 0; it < 2; it++) {
        int idx = tid + it*256;
        int r = idx >> 3, k4 = idx & 7;
        float4 t = *(const float4*)(X + (size_t)(row0 + r)*Cdim + kc*32 + k4*4);
        *(float4*)(sA + r*SASTR + k4*4) = t;
    }
}
__device__ __forceinline__ void load_tileB(float* sB, const float* __restrict__ W,
                                           int kc, int tid) {
    #pragma unroll
    for (int it = 0; it < 8; it++) {
        int idx = tid + it*256;
        int c = idx >> 3, k4 = idx & 7;
        float4 t = *(const float4*)(W + c*Cdim + kc*32 + k4*4);
        sB[(k4*4+0)*SBSTR + c] = t.x;
        sB[(k4*4+1)*SBSTR + c] = t.y;
        sB[(k4*4+2)*SBSTR + c] = t.z;
        sB[(k4*4+3)*SBSTR + c] = t.w;
    }
}
__device__ __forceinline__ void mma_chunk_sA(const float* sA, const float* sB,
                                             float acc[8][8], int tx, int ty) {
    #pragma unroll
    for (int k = 0; k < 32; k++) {
        float a[8];
        #pragma unroll
        for (int mm = 0; mm < 4; mm++) {
            a[mm]   = sA[(ty*4+mm)*SASTR + k];
            a[4+mm] = sA[(32+ty*4+mm)*SASTR + k];
        }
        float4 p0 = *(const float4*)(sB + k*SBSTR + tx*4);
        float4 p1 = *(const float4*)(sB + k*SBSTR + 128 + tx*4);
        float bb[8] = {p0.x,p0.y,p0.z,p0.w,p1.x,p1.y,p1.z,p1.w};
        #pragma unroll
        for (int m = 0; m < 8; m++)
            #pragma unroll
            for (int n = 0; n < 8; n++)
                acc[m][n] = fmaf(a[m], bb[n], acc[m][n]);
    }
}

__global__ __launch_bounds__(256) void proj_kernel(
    const float* __restrict__ X,
    const float* __restrict__ W0, const float* __restrict__ b0,
    const float* __restrict__ W1, const float* __restrict__ b1,
    const float* __restrict__ W2, const float* __restrict__ b2)
{
    __shared__ float sA[64*SASTR];
    __shared__ float sB[32*SBSTR];
    int which = blockIdx.y;
    const float* W    = (which==0) ? W0 : (which==1 ? W1 : W2);
    const float* bias = (which==0) ? b0 : (which==1 ? b1 : b2);

    int tid = threadIdx.x;
    int tx = tid & 31, ty = tid >> 5;
    int row0 = blockIdx.x * 64;

    float acc[8][8];
    #pragma unroll
    for (int m = 0; m < 8; m++)
        #pragma unroll
        for (int n = 0; n < 8; n++) acc[m][n] = 0.f;

    for (int kc = 0; kc < 8; kc++) {
        __syncthreads();
        load_tileA(sA, X, row0, kc, tid);
        load_tileB(sB, W, kc, tid);
        __syncthreads();
        mma_chunk_sA(sA, sB, acc, tx, ty);
    }
    #pragma unroll
    for (int mh = 0; mh < 2; mh++)
    #pragma unroll
    for (int mm = 0; mm < 4; mm++) {
        int m = mh*4 + mm;
        int rloc = mh*32 + ty*4 + mm;
        size_t grow = (size_t)(row0 + rloc) * Cdim;
        #pragma unroll
        for (int nh = 0; nh < 2; nh++) {
            int col0 = nh*128 + tx*4;
            float4 o;
            o.x = acc[m][nh*4+0] + bias[col0+0];
            o.y = acc[m][nh*4+1] + bias[col0+1];
            o.z = acc[m][nh*4+2] + bias[col0+2];
            o.w = acc[m][nh*4+3] + bias[col0+3];
            if (which == 0)      *(float4*)(g_q + grow + col0) = o;
            else if (which == 1) *(float4*)(g_k + grow + col0) = o;
            else {
                __half2 h0 = __floats2half2_rn(o.x, o.y);
                __half2 h1 = __floats2half2_rn(o.z, o.w);
                uint2 u;
                u.x = *reinterpret_cast<uint32_t*>(&h0);
                u.y = *reinterpret_cast<uint32_t*>(&h1);
                *(uint2*)(g_v16 + grow + col0) = u;
            }
        }
    }
}

// ---------------- edge kernel cp.async loaders (256 threads) ----------------
__device__ __forceinline__ void loadWe(uint32_t sb, int nc, int tid) {
    const __half* sh = g_We_h + (size_t)nc*64*Cdim;
    #pragma unroll
    for (int it = 0; it < 8; it++) {            // 64 rows x 32 parts
        int idx = tid + it*256;
        int row = idx >> 5, part = idx & 31;
        cp16(sb + WB + row*528 + part*16, sh + row*Cdim + part*8);
    }
}
__device__ __forceinline__ void loadWoe(uint32_t sb, int nc, int tid) {
    #pragma unroll
    for (int it = 0; it < 8; it++) {            // 256 rows x 8 parts
        int idx = tid + it*256;
        int row = idx >> 3, part = idx & 7;
        cp16(sb + WB + row*144 + part*16, g_Woe_h + row*Cdim + nc*64 + part*8);
    }
}

// ---------------- GEMM passes ----------------
__device__ __forceinline__ void g1(uint32_t aA, uint32_t bH, float acc[4][4]) {
    uint32_t a[4], bh[4];
    #pragma unroll
    for (int ks = 0; ks < 16; ks++) {
        ldm4(aA + ks*32, a);
        #pragma unroll
        for (int ntp = 0; ntp < 2; ntp++) {
            ldm4(bH + ntp*(16*528) + ks*32, bh);
            mma_f16(acc[ntp*2+0], a, bh[0], bh[1]);
            mma_f16(acc[ntp*2+1], a, bh[2], bh[3]);
        }
    }
}
__device__ __forceinline__ void g2(uint32_t aA, uint32_t bH, float acc[16][4]) {
    uint32_t a[4], bh[4];
    #pragma unroll
    for (int ks = 0; ks < 4; ks++) {
        ldm4(aA + ks*32, a);
        #pragma unroll
        for (int ntp = 0; ntp < 8; ntp++) {
            ldm4(bH + ntp*(16*144) + ks*32, bh);
            mma_f16(acc[ntp*2+0], a, bh[0], bh[1]);
            mma_f16(acc[ntp*2+1], a, bh[2], bh[3]);
        }
    }
}

// ---------------- fused edge mega-kernel: one CTA per (b,i,j-half) ----------------
__global__ __launch_bounds__(256, 2) void edge_fused(
    const float* __restrict__ edge,
    const float* __restrict__ be, const float* __restrict__ boe,
    const float* __restrict__ bon,
    float* __restrict__ edge_out, float* __restrict__ node_out)
{
    extern __shared__ char sm[];
    __shared__ int sWin;
    uint32_t sb = smem_u32(sm);
    const int tid  = threadIdx.x;
    const int lane = tid & 31, wid = tid >> 5;
    const int bi   = blockIdx.x >> 1;       // b*128 + i
    const int jh   = blockIdx.x & 1;        // j-half
    const int b    = bi >> 7;
    const int jrow0 = jh * 64;

    loadWe(sb, 0, tid);
    CP_COMMIT;

    float* sQ   = (float*)(sm + SQ_);
    float* sBe  = (float*)(sm + SBE_);
    float* sBoe = (float*)(sm + SBOE_);
    float* sAgg = (float*)(sm + SAGG_);
    sQ[tid]   = g_q[(size_t)bi*Cdim + tid];
    sBe[tid]  = be[tid];
    sBoe[tid] = boe[tid];

    // edge half-tile -> fp16 in smem (64 rows x 256 cols)
    const float4* erow = (const float4*)(edge + ((size_t)bi*Ndim + jrow0)*Cdim);
    #pragma unroll
    for (int it = 0; it < 16; it++) {
        int idx = tid + it*256;              // 0..4095 float4
        float4 v = erow[idx];
        int j = idx >> 6, c4 = idx & 63;
        __half2 h0 = __floats2half2_rn(v.x, v.y);
        __half2 h1 = __floats2half2_rn(v.z, v.w);
        uint2 u;
        u.x = *reinterpret_cast<uint32_t*>(&h0);
        u.y = *reinterpret_cast<uint32_t*>(&h1);
        *(uint2*)(sm + EDG + j*528 + c4*8) = u;
    }

    // fragment address offsets (8 warps: wm 0..3 m-tiles, wn 0..1 n-groups)
    const int wm = wid & 3, wn = wid >> 2;
    const int m0 = wm*16;
    const uint32_t aoff  = (uint32_t)((m0 + (lane & 15))*528 + ((lane >> 4) << 4));
    const uint32_t atoff = (uint32_t)((m0 + (lane & 15))*144 + ((lane >> 4) << 4));
    const uint32_t b1off = (uint32_t)((wn*32  + (lane & 7) + ((lane & 16) ? 8 : 0))*528 + ((lane & 8) << 1));
    const uint32_t b2off = (uint32_t)((wn*128 + (lane & 7) + ((lane & 16) ? 8 : 0))*144 + ((lane & 8) << 1));

    float acc2[16][4];
    #pragma unroll
    for (int i = 0; i < 16; i++)
        #pragma unroll
        for (int r = 0; r < 4; r++) acc2[i][r] = 0.f;

    const int r0 = m0 + (lane >> 2);         // local row 0..63

    for (int nc = 0; nc < 4; nc++) {
        float acc1[4][4];
        #pragma unroll
        for (int i = 0; i < 4; i++)
            #pragma unroll
            for (int r = 0; r < 4; r++) acc1[i][r] = 0.f;

        CP_WAIT0; __syncthreads();            // We(nc) ready (nc=0: +edge STS visible)
        g1(sb + EDG + aoff, sb + WB + b1off, acc1);
        __syncthreads();                      // all done reading WB
        loadWoe(sb, nc, tid); CP_COMMIT;      // overlaps gating epilogue

        // ---- gating epilogue -> attn fp16 chunk nc ----
        #pragma unroll
        for (int nt = 0; nt < 4; nt++) {
            int c_loc = wn*32 + nt*8 + ((lane & 3) << 1);
            int c = nc*64 + c_loc;
            float q0 = sQ[c], q1 = sQ[c+1];
            float be0 = sBe[c], be1 = sBe[c+1];
            float2 k0 = *(const float2*)(g_k + (size_t)(b*Ndim + jrow0 + r0)*Cdim + c);
            float2 k1 = *(const float2*)(g_k + (size_t)(b*Ndim + jrow0 + r0 + 8)*Cdim + c);
            float e00 = acc1[nt][0] + be0, e01 = acc1[nt][1] + be1;
            float e10 = acc1[nt][2] + be0, e11 = acc1[nt][3] + be1;
            float a00 = q0*k0.x*INVS*(e00*e00 + e00);
            float a01 = q1*k0.y*INVS*(e01*e01 + e01);
            float a10 = q0*k1.x*INVS*(e10*e10 + e10);
            float a11 = q1*k1.y*INVS*(e11*e11 + e11);
            *(uint32_t*)(sm + ATT + nc*9216 + r0*144 + c_loc*2)     = hpk(a00, a01);
            *(uint32_t*)(sm + ATT + nc*9216 + (r0+8)*144 + c_loc*2) = hpk(a10, a11);
        }

        CP_WAIT0; __syncthreads();            // Woe(nc) ready + attn chunk visible
        g2(sb + ATT + nc*9216 + atoff, sb + WB + b2off, acc2);
        __syncthreads();                      // all done reading WB
        if (nc < 3) { loadWe(sb, nc+1, tid); CP_COMMIT; }
    }

    // ---- edge_out epilogue ----
    {
        float* out0 = edge_out + ((size_t)bi*Ndim + jrow0 + r0)*Cdim;
        float* out1 = out0 + 8*Cdim;
        #pragma unroll
        for (int nt = 0; nt < 16; nt++) {
            int n = wn*128 + nt*8 + ((lane & 3) << 1);
            float2 o0, o1;
            o0.x = acc2[nt][0] + sBoe[n];   o0.y = acc2[nt][1] + sBoe[n+1];
            o1.x = acc2[nt][2] + sBoe[n];   o1.y = acc2[nt][3] + sBoe[n+1];
            *(float2*)(out0 + n) = o0;
            *(float2*)(out1 + n) = o1;
        }
    }

    // ---- local softmax partials over 64 j (no max subtraction; range safe in fp32) ----
    float s = 0.f, ag = 0.f;
    {
        int c = tid;
        int ch = c >> 6, off = c & 63;
        const __half* vbase = g_v16 + (size_t)(b*Ndim + jrow0)*Cdim + c;
        #pragma unroll 4
        for (int j = 0; j < 64; j++) {
            float a = __half2float(*(const __half*)(sm + ATT + ch*9216 + j*144 + off*2));
            float p = __expf(a);
            s += p;
            ag += p * __half2float(vbase[(size_t)j*Cdim]);
        }
        g_ps [(size_t)jh*BN*Cdim + (size_t)bi*Cdim + c] = s;
        g_pag[(size_t)jh*BN*Cdim + (size_t)bi*Cdim + c] = ag;
    }

    // ---- second-arriving CTA per bi combines partials + node matvec ----
    __threadfence();
    __syncthreads();
    if (tid == 0) {
        int old = atomicAdd(&g_cnt[bi], 1);
        sWin = (old == 1);
        if (old == 1) g_cnt[bi] = 0;          // self-reset for next launch
    }
    __syncthreads();
    if (sWin) {
        __threadfence();                       // acquire other CTA's partials
        int c = tid;
        float so = g_ps [(size_t)(jh^1)*BN*Cdim + (size_t)bi*Cdim + c];
        float ao = g_pag[(size_t)(jh^1)*BN*Cdim + (size_t)bi*Cdim + c];
        sAgg[c] = (ag + ao) / (s + so);
        __syncthreads();
        float acc = bon[c];
        #pragma unroll 8
        for (int k = 0; k < Cdim; k++)
            acc = fmaf(sAgg[k], g_WonT[(size_t)k*Cdim + c], acc);
        node_out[(size_t)bi*Cdim + c] = acc;
    }
}

// ---------------- launch ----------------
extern "C" void kernel_launch(void* const* d_in, const int* in_sizes, int n_in,
                              void* d_out, int out_size)
{
    const float* node = (const float*)d_in[0];
    const float* edge = (const float*)d_in[1];
    const float* Wq  = (const float*)d_in[2];  const float* bq  = (const float*)d_in[3];
    const float* Wk  = (const float*)d_in[4];  const float* bk  = (const float*)d_in[5];
    const float* Wv  = (const float*)d_in[6];  const float* bv  = (const float*)d_in[7];
    const float* We  = (const float*)d_in[8];  const float* be  = (const float*)d_in[9];
    const float* Woe = (const float*)d_in[10]; const float* boe = (const float*)d_in[11];
    const float* Won = (const float*)d_in[12]; const float* bon = (const float*)d_in[13];

    float* out = (float*)d_out;
    float* node_out = out;                       // [B,N,C]
    float* edge_out = out + (size_t)BN*Cdim;     // [B,N,N,C]

    cudaFuncSetAttribute(edge_fused, cudaFuncAttributeMaxDynamicSharedMemorySize, ESMEM);

    prep_w<<<dim3(Cdim, 3), Cdim>>>(We, Woe, Won);
    proj_kernel<<<dim3(BN/64, 3), 256>>>(node, Wq, bq, Wk, bk, Wv, bv);
    edge_fused<<<2*BN, 256, ESMEM>>>(edge, be, boe, bon, edge_out, node_out);
}